// round 13
// baseline (speedup 1.0000x reference)
#include <cuda_runtime.h>
#include <cuda_bf16.h>

// PointInstanceNorm — two-pass; reduce folds finalize via last-block-done.
// x: [N,D] fp32; seqlen: [B+1] cumulative; weight/bias: [D].
// out[i,d] = (x[i,d]-mean[b,d]) * rsqrt(var[b,d]+eps) * w[d] + bias[d].
//
// R7 (250.4us): reduce 84.2us @6.13TB/s, norm 153.5us @ceiling, ~12.7us of
// finalize + launch gaps. R9 removes the separate finalize kernel: the last
// reduce block to finish sums the (L2-hot) per-chunk partials and writes
// scale/shift directly. Reduce/norm inner loops byte-identical to R7.

#define PIN_EPS 1e-5f
#define PIN_MAXBD   (1 << 20)
#define PIN_PARTCAP (1 << 22)

__device__ float g_psum [PIN_PARTCAP];
__device__ float g_psq  [PIN_PARTCAP];
__device__ float g_scale[PIN_MAXBD];
__device__ float g_shift[PIN_MAXBD];
__device__ unsigned g_done = 0;        // last-block ticket (reset each run)
// scalar-fallback scratch
__device__ float g_sum[PIN_MAXBD];
__device__ float g_sq [PIN_MAXBD];

// ---------------------------------------------------------------------------
// Pass 1: reduce + fused finalize. grid=(chunks,B) sized to ONE wave.
// block=256. 2-way unroll, per-(chunk,b) partials, no atomics on data.
// ---------------------------------------------------------------------------
__global__ void __launch_bounds__(256)
pin_reduce_kernel(const float* __restrict__ x,
                  const int*   __restrict__ seqlen,
                  const float* __restrict__ w,
                  const float* __restrict__ bias,
                  int D4, int B, int BD) {
    const int c  = blockIdx.x;
    const int b  = blockIdx.y;
    const long long s = seqlen[b];
    const long long e = seqlen[b + 1];
    const int L  = (int)(e - s);
    const int nb = gridDim.x;
    const int chunk = (L + nb - 1) / nb;
    const long long r0 = s + (long long)c * chunk;
    const long long r1 = s + (long long)min((long long)L,
                                            (long long)(c + 1) * (long long)chunk);
    const int tid  = threadIdx.x;
    const int lane = tid % D4;
    const int grp  = tid / D4;
    const int ngrp = blockDim.x / D4;
    const int D    = D4 * 4;

    float4 s0 = make_float4(0.f, 0.f, 0.f, 0.f), s1 = s0;
    float4 q0 = s0, q1 = s0;

    if (grp < ngrp) {
        const float4* __restrict__ x4 = (const float4*)x;
        const long long step = ngrp;
        long long r = r0 + grp;
        for (; r + step < r1; r += 2 * step) {
            float4 v0 = x4[(r       ) * D4 + lane];
            float4 v1 = x4[(r + step) * D4 + lane];
            s0.x += v0.x; s0.y += v0.y; s0.z += v0.z; s0.w += v0.w;
            q0.x += v0.x * v0.x; q0.y += v0.y * v0.y;
            q0.z += v0.z * v0.z; q0.w += v0.w * v0.w;
            s1.x += v1.x; s1.y += v1.y; s1.z += v1.z; s1.w += v1.w;
            q1.x += v1.x * v1.x; q1.y += v1.y * v1.y;
            q1.z += v1.z * v1.z; q1.w += v1.w * v1.w;
        }
        if (r < r1) {
            float4 v = x4[r * D4 + lane];
            s0.x += v.x; s0.y += v.y; s0.z += v.z; s0.w += v.w;
            q0.x += v.x * v.x; q0.y += v.y * v.y;
            q0.z += v.z * v.z; q0.w += v.w * v.w;
        }
    }
    s0.x += s1.x; s0.y += s1.y; s0.z += s1.z; s0.w += s1.w;
    q0.x += q1.x; q0.y += q1.y; q0.z += q1.z; q0.w += q1.w;

    __shared__ float4 sh_s[256];
    __shared__ float4 sh_q[256];
    sh_s[tid] = s0;
    sh_q[tid] = q0;
    __syncthreads();

    if (grp == 0) {
        for (int g = 1; g < ngrp; g++) {
            float4 a  = sh_s[g * D4 + lane];
            float4 cq = sh_q[g * D4 + lane];
            s0.x += a.x;  s0.y += a.y;  s0.z += a.z;  s0.w += a.w;
            q0.x += cq.x; q0.y += cq.y; q0.z += cq.z; q0.w += cq.w;
        }
        const long long o = (long long)c * BD + b * D + lane * 4;
        ((float4*)(g_psum + o))[0] = s0;
        ((float4*)(g_psq  + o))[0] = q0;
    }

    // ---- last-block-done fused finalize ----
    __threadfence();                       // publish partials
    __shared__ bool is_last;
    if (tid == 0) {
        unsigned total = gridDim.x * gridDim.y;
        unsigned t = atomicAdd(&g_done, 1u);
        is_last = (t == total - 1u);
    }
    __syncthreads();
    if (!is_last) return;
    __threadfence();                       // acquire all partials

    const int chunks = gridDim.x;
    for (int i0 = tid * 4; i0 < BD; i0 += blockDim.x * 4) {
        float4 sum = make_float4(0.f, 0.f, 0.f, 0.f);
        float4 sq  = sum;
        for (int cc = 0; cc < chunks; cc++) {
            const long long o = (long long)cc * BD + i0;
            float4 a  = *(const float4*)(g_psum + o);
            float4 cq = *(const float4*)(g_psq  + o);
            sum.x += a.x;  sum.y += a.y;  sum.z += a.z;  sum.w += a.w;
            sq.x  += cq.x; sq.y  += cq.y; sq.z  += cq.z; sq.w  += cq.w;
        }
        const int bb = i0 / D;
        const int dd = i0 - bb * D;
        const float denom = fmaxf((float)(seqlen[bb + 1] - seqlen[bb]), 1.0f);
        const float inv_n = 1.0f / denom;
        float4 wv = *(const float4*)(w    + dd);
        float4 bv = *(const float4*)(bias + dd);
        float4 mean, scl, shf;
        mean.x = sum.x * inv_n; mean.y = sum.y * inv_n;
        mean.z = sum.z * inv_n; mean.w = sum.w * inv_n;
        scl.x = rsqrtf(fmaxf(sq.x * inv_n - mean.x * mean.x, 0.f) + PIN_EPS) * wv.x;
        scl.y = rsqrtf(fmaxf(sq.y * inv_n - mean.y * mean.y, 0.f) + PIN_EPS) * wv.y;
        scl.z = rsqrtf(fmaxf(sq.z * inv_n - mean.z * mean.z, 0.f) + PIN_EPS) * wv.z;
        scl.w = rsqrtf(fmaxf(sq.w * inv_n - mean.w * mean.w, 0.f) + PIN_EPS) * wv.w;
        shf.x = bv.x - mean.x * scl.x;
        shf.y = bv.y - mean.y * scl.y;
        shf.z = bv.z - mean.z * scl.z;
        shf.w = bv.w - mean.w * scl.w;
        *(float4*)(g_scale + i0) = scl;
        *(float4*)(g_shift + i0) = shf;
    }
    if (tid == 0) g_done = 0;              // replay-idempotent
}

// ---------------------------------------------------------------------------
// Pass 2: normalize — EXACT R3 form (153.5us @ ceiling).
// ---------------------------------------------------------------------------
__global__ void __launch_bounds__(256)
pin_norm_kernel(const float* __restrict__ x,
                const int*   __restrict__ seqlen,
                float*       __restrict__ out,
                int D4) {
    const int b = blockIdx.y;
    const long long s = seqlen[b];
    const long long e = seqlen[b + 1];
    const int L  = (int)(e - s);
    const int nb = gridDim.x;
    const int chunk = (L + nb - 1) / nb;
    const long long r0 = s + (long long)blockIdx.x * chunk;
    const long long r1 = s + (long long)min((long long)L,
                                            (long long)(blockIdx.x + 1) * (long long)chunk);
    const int lane = threadIdx.x % D4;
    const int grp  = threadIdx.x / D4;
    const int ngrp = blockDim.x / D4;
    if (grp >= ngrp) return;

    const float4 sc = ((const float4*)g_scale)[b * D4 + lane];
    const float4 sh = ((const float4*)g_shift)[b * D4 + lane];
    const float4* __restrict__ x4 = (const float4*)x;
    float4* __restrict__ o4 = (float4*)out;

    for (long long r = r0 + grp; r < r1; r += ngrp) {
        float4 v = x4[r * D4 + lane];
        float4 o;
        o.x = fmaf(v.x, sc.x, sh.x);
        o.y = fmaf(v.y, sc.y, sh.y);
        o.z = fmaf(v.z, sc.z, sh.z);
        o.w = fmaf(v.w, sc.w, sh.w);
        o4[r * D4 + lane] = o;
    }
}

// ---------------------------------------------------------------------------
// Scalar fallback (any shape).
// ---------------------------------------------------------------------------
__global__ void pin_zero_kernel(int n) {
    int i = blockIdx.x * blockDim.x + threadIdx.x;
    if (i < n) { g_sum[i] = 0.0f; g_sq[i] = 0.0f; }
}

__global__ void pin_reduce_scalar(const float* __restrict__ x,
                                  const int*   __restrict__ seqlen, int D) {
    const int b = blockIdx.y;
    const int s = seqlen[b];
    const int e = seqlen[b + 1];
    const int L = e - s;
    const int nb = gridDim.x;
    const int chunk = (L + nb - 1) / nb;
    long long r0 = (long long)s + (long long)blockIdx.x * chunk;
    long long r1 = (long long)s + (long long)min((long long)L,
                                                 (long long)(blockIdx.x + 1) * (long long)chunk);
    for (int d = threadIdx.x; d < D; d += blockDim.x) {
        float sum = 0.f, sq = 0.f;
        for (long long r = r0; r < r1; r++) {
            float v = x[r * D + d];
            sum += v; sq += v * v;
        }
        atomicAdd(&g_sum[b * D + d], sum);
        atomicAdd(&g_sq [b * D + d], sq);
    }
}

__global__ void pin_finalize_scalar(const int*   __restrict__ seqlen,
                                    const float* __restrict__ w,
                                    const float* __restrict__ bias,
                                    int B, int D) {
    int i = blockIdx.x * blockDim.x + threadIdx.x;
    if (i >= B * D) return;
    int b = i / D;
    int d = i - b * D;
    float denom = fmaxf((float)(seqlen[b + 1] - seqlen[b]), 1.0f);
    float mean  = g_sum[i] / denom;
    float var   = fmaxf(g_sq[i] / denom - mean * mean, 0.0f);
    float sc = rsqrtf(var + PIN_EPS) * w[d];
    g_scale[i] = sc;
    g_shift[i] = bias[d] - mean * sc;
}

__global__ void pin_norm_scalar(const float* __restrict__ x,
                                const int*   __restrict__ seqlen,
                                float*       __restrict__ out, int D) {
    const int b = blockIdx.y;
    const int s = seqlen[b];
    const int e = seqlen[b + 1];
    const int L = e - s;
    const int nb = gridDim.x;
    const int chunk = (L + nb - 1) / nb;
    long long r0 = (long long)s + (long long)blockIdx.x * chunk;
    long long r1 = (long long)s + (long long)min((long long)L,
                                                 (long long)(blockIdx.x + 1) * (long long)chunk);
    for (long long r = r0; r < r1; r++) {
        for (int d = threadIdx.x; d < D; d += blockDim.x) {
            float v = x[r * D + d];
            out[r * D + d] = fmaf(v, g_scale[b * D + d], g_shift[b * D + d]);
        }
    }
}

extern "C" void kernel_launch(void* const* d_in, const int* in_sizes, int n_in,
                              void* d_out, int out_size) {
    const float* x      = (const float*)d_in[0];
    const int*   seqlen = (const int*)  d_in[1];
    const float* weight = (const float*)d_in[2];
    const float* bias   = (const float*)d_in[3];
    float*       out    = (float*)d_out;

    const int D  = in_sizes[2];          // weight is [1, D]
    const int B  = in_sizes[1] - 1;      // seqlen is [B+1]
    const long long N = (D > 0) ? (long long)in_sizes[0] / D : 0;
    const int BD = B * D;

    const int D4 = D / 4;
    const bool vec_ok = (D > 0) && (D % 4 == 0) && (D4 >= 1) && (D4 <= 256) &&
                        (BD > 0) && (BD <= PIN_MAXBD);

    if (vec_ok) {
        // ---- reduce: one resident wave ----
        int dev = 0, sms = 0, per_sm = 0;
        cudaGetDevice(&dev);
        cudaDeviceGetAttribute(&sms, cudaDevAttrMultiProcessorCount, dev);
        cudaOccupancyMaxActiveBlocksPerMultiprocessor(&per_sm, pin_reduce_kernel,
                                                      256, 0);
        if (sms <= 0) sms = 148;
        if (per_sm <= 0) per_sm = 4;
        int rchunks = (sms * per_sm) / B;            // one wave total
        if (rchunks < 1) rchunks = 1;
        long long avg_rows = (N + B - 1) / B;
        if ((long long)rchunks > avg_rows && avg_rows > 0)
            rchunks = (int)avg_rows;
        while ((long long)rchunks * BD > PIN_PARTCAP && rchunks > 1)
            rchunks >>= 1;

        // ---- norm: R3 config (~4096 blocks) ----
        int nchunks = (4096 + B - 1) / B;
        if ((long long)nchunks > avg_rows && avg_rows > 0)
            nchunks = (int)avg_rows;
        if (nchunks < 1) nchunks = 1;

        dim3 rgrid(rchunks, B);
        dim3 ngrid(nchunks, B);

        pin_reduce_kernel<<<rgrid, 256>>>(x, seqlen, weight, bias, D4, B, BD);
        pin_norm_kernel<<<ngrid, 256>>>(x, seqlen, out, D4);
        return;
    }

    // ---- Fallback: scalar 4-kernel pipeline (any shape) ----
    {
        int threads = 256;
        int blocks = (BD + threads - 1) / threads;
        if (blocks < 1) blocks = 1;
        pin_zero_kernel<<<blocks, threads>>>(BD);
    }
    int Bx = (B > 0) ? B : 1;
    int ch = (4096 + Bx - 1) / Bx;
    long long avg_rows = (N + Bx - 1) / Bx;
    if ((long long)ch > avg_rows && avg_rows > 0) ch = (int)avg_rows;
    if (ch < 1) ch = 1;
    dim3 grid(ch, Bx);
    pin_reduce_scalar<<<grid, 256>>>(x, seqlen, D);
    {
        int threads = 256;
        int blocks = (BD + threads - 1) / threads;
        if (blocks < 1) blocks = 1;
        pin_finalize_scalar<<<blocks, threads>>>(seqlen, weight, bias, B, D);
    }
    pin_norm_scalar<<<grid, 256>>>(x, seqlen, out, D);
}

// round 14
// speedup vs baseline: 1.0227x; 1.0227x over previous
#include <cuda_runtime.h>
#include <cuda_bf16.h>

// PointInstanceNorm — two-pass, TWO kernels total.
// x: [N,D] fp32; seqlen: [B+1] cumulative; weight/bias: [D].
// out[i,d] = (x[i,d]-mean[b,d]) * rsqrt(var[b,d]+eps) * w[d] + bias[d].
//
// R9-12 lesson: fusing finalize into the REDUCE kernel (last-block-done)
// regressed reduce ~28us (reg pressure + fence/ticket on critical path).
// R13: reduce reverted to exact R7 form (84.2us @6.13TB/s). Finalize moves
// into the NORM kernel's prologue, computed REDUNDANTLY per block from the
// L2-hot per-chunk partials (~933KB): each block sums chunks for its own
// segment's 128 channels (~1-2us, overlapped). Removes the finalize kernel
// and two dependency gaps (~12.7us -> ~2us).

#define PIN_EPS 1e-5f
#define PIN_MAXBD   (1 << 20)
#define PIN_PARTCAP (1 << 22)

__device__ float g_psum [PIN_PARTCAP];
__device__ float g_psq  [PIN_PARTCAP];
// scalar-fallback scratch
__device__ float g_sum  [PIN_MAXBD];
__device__ float g_sq   [PIN_MAXBD];
__device__ float g_scale[PIN_MAXBD];
__device__ float g_shift[PIN_MAXBD];

// ---------------------------------------------------------------------------
// Pass 1: reduce — EXACT R7 form. grid=(chunks,B) sized to ONE wave,
// block=256, 2-way unroll, per-(chunk,b) partials, no atomics.
// ---------------------------------------------------------------------------
__global__ void __launch_bounds__(256)
pin_reduce_kernel(const float* __restrict__ x,
                  const int*   __restrict__ seqlen,
                  int D4, int BD) {
    const int c  = blockIdx.x;
    const int b  = blockIdx.y;
    const long long s = seqlen[b];
    const long long e = seqlen[b + 1];
    const int L  = (int)(e - s);
    const int nb = gridDim.x;
    const int chunk = (L + nb - 1) / nb;
    const long long r0 = s + (long long)c * chunk;
    const long long r1 = s + (long long)min((long long)L,
                                            (long long)(c + 1) * (long long)chunk);
    const int lane = threadIdx.x % D4;
    const int grp  = threadIdx.x / D4;
    const int ngrp = blockDim.x / D4;
    const int D    = D4 * 4;

    float4 s0 = make_float4(0.f, 0.f, 0.f, 0.f), s1 = s0;
    float4 q0 = s0, q1 = s0;

    if (grp < ngrp) {
        const float4* __restrict__ x4 = (const float4*)x;
        const long long step = ngrp;
        long long r = r0 + grp;
        for (; r + step < r1; r += 2 * step) {
            float4 v0 = x4[(r       ) * D4 + lane];
            float4 v1 = x4[(r + step) * D4 + lane];
            s0.x += v0.x; s0.y += v0.y; s0.z += v0.z; s0.w += v0.w;
            q0.x += v0.x * v0.x; q0.y += v0.y * v0.y;
            q0.z += v0.z * v0.z; q0.w += v0.w * v0.w;
            s1.x += v1.x; s1.y += v1.y; s1.z += v1.z; s1.w += v1.w;
            q1.x += v1.x * v1.x; q1.y += v1.y * v1.y;
            q1.z += v1.z * v1.z; q1.w += v1.w * v1.w;
        }
        if (r < r1) {
            float4 v = x4[r * D4 + lane];
            s0.x += v.x; s0.y += v.y; s0.z += v.z; s0.w += v.w;
            q0.x += v.x * v.x; q0.y += v.y * v.y;
            q0.z += v.z * v.z; q0.w += v.w * v.w;
        }
    }
    s0.x += s1.x; s0.y += s1.y; s0.z += s1.z; s0.w += s1.w;
    q0.x += q1.x; q0.y += q1.y; q0.z += q1.z; q0.w += q1.w;

    __shared__ float4 sh_s[256];
    __shared__ float4 sh_q[256];
    sh_s[threadIdx.x] = s0;
    sh_q[threadIdx.x] = q0;
    __syncthreads();

    if (grp == 0) {
        for (int g = 1; g < ngrp; g++) {
            float4 a  = sh_s[g * D4 + lane];
            float4 cq = sh_q[g * D4 + lane];
            s0.x += a.x;  s0.y += a.y;  s0.z += a.z;  s0.w += a.w;
            q0.x += cq.x; q0.y += cq.y; q0.z += cq.z; q0.w += cq.w;
        }
        const long long o = (long long)c * BD + b * (D4 * 4) + lane * 4;
        ((float4*)(g_psum + o))[0] = s0;
        ((float4*)(g_psq  + o))[0] = q0;
    }
}

// ---------------------------------------------------------------------------
// Pass 2: normalize with per-block redundant finalize prologue.
// Streaming loop is byte-identical to the R3/R7 norm (151.7us measured).
// ---------------------------------------------------------------------------
__global__ void __launch_bounds__(256)
pin_norm_kernel(const float* __restrict__ x,
                const int*   __restrict__ seqlen,
                const float* __restrict__ w,
                const float* __restrict__ bias,
                float*       __restrict__ out,
                int D4, int BD, int chunks) {
    const int b = blockIdx.y;
    const long long s = seqlen[b];
    const long long e = seqlen[b + 1];
    const int L  = (int)(e - s);
    const int nb = gridDim.x;
    const int chunk = (L + nb - 1) / nb;
    const long long r0 = s + (long long)blockIdx.x * chunk;
    const long long r1 = s + (long long)min((long long)L,
                                            (long long)(blockIdx.x + 1) * (long long)chunk);
    const int tid  = threadIdx.x;
    const int lane = tid % D4;
    const int grp  = tid / D4;
    const int ngrp = blockDim.x / D4;
    const int D    = D4 * 4;

    // ---- prologue: finalize this segment's scale/shift from L2-hot partials ----
    __shared__ float4 sh_s[256];
    __shared__ float4 sh_q[256];
    __shared__ float4 sh_scale[256];   // indexed by lane (D4 <= 256)
    __shared__ float4 sh_shift[256];

    float4 ps = make_float4(0.f, 0.f, 0.f, 0.f);
    float4 pq = ps;
    if (grp < ngrp) {
        for (int c = grp; c < chunks; c += ngrp) {
            const long long o = (long long)c * BD + b * D + lane * 4;
            float4 a  = *(const float4*)(g_psum + o);
            float4 cq = *(const float4*)(g_psq  + o);
            ps.x += a.x;  ps.y += a.y;  ps.z += a.z;  ps.w += a.w;
            pq.x += cq.x; pq.y += cq.y; pq.z += cq.z; pq.w += cq.w;
        }
    }
    sh_s[tid] = ps;
    sh_q[tid] = pq;
    __syncthreads();
    if (grp == 0) {
        for (int g = 1; g < ngrp; g++) {
            float4 a  = sh_s[g * D4 + lane];
            float4 cq = sh_q[g * D4 + lane];
            ps.x += a.x;  ps.y += a.y;  ps.z += a.z;  ps.w += a.w;
            pq.x += cq.x; pq.y += cq.y; pq.z += cq.z; pq.w += cq.w;
        }
        const float inv_n = 1.0f / fmaxf((float)(e - s), 1.0f);
        float4 wv = __ldg(((const float4*)w)    + lane);
        float4 bv = __ldg(((const float4*)bias) + lane);
        float4 mean, scl, shf;
        mean.x = ps.x * inv_n; mean.y = ps.y * inv_n;
        mean.z = ps.z * inv_n; mean.w = ps.w * inv_n;
        scl.x = rsqrtf(fmaxf(pq.x * inv_n - mean.x * mean.x, 0.f) + PIN_EPS) * wv.x;
        scl.y = rsqrtf(fmaxf(pq.y * inv_n - mean.y * mean.y, 0.f) + PIN_EPS) * wv.y;
        scl.z = rsqrtf(fmaxf(pq.z * inv_n - mean.z * mean.z, 0.f) + PIN_EPS) * wv.z;
        scl.w = rsqrtf(fmaxf(pq.w * inv_n - mean.w * mean.w, 0.f) + PIN_EPS) * wv.w;
        shf.x = bv.x - mean.x * scl.x;
        shf.y = bv.y - mean.y * scl.y;
        shf.z = bv.z - mean.z * scl.z;
        shf.w = bv.w - mean.w * scl.w;
        sh_scale[lane] = scl;
        sh_shift[lane] = shf;
    }
    __syncthreads();

    if (grp >= ngrp) return;
    const float4 sc = sh_scale[lane];
    const float4 sh = sh_shift[lane];

    // ---- streaming loop: exact R3/R7 form ----
    const float4* __restrict__ x4 = (const float4*)x;
    float4* __restrict__ o4 = (float4*)out;
    for (long long r = r0 + grp; r < r1; r += ngrp) {
        float4 v = x4[r * D4 + lane];
        float4 o;
        o.x = fmaf(v.x, sc.x, sh.x);
        o.y = fmaf(v.y, sc.y, sh.y);
        o.z = fmaf(v.z, sc.z, sh.z);
        o.w = fmaf(v.w, sc.w, sh.w);
        o4[r * D4 + lane] = o;
    }
}

// ---------------------------------------------------------------------------
// Scalar fallback (any shape).
// ---------------------------------------------------------------------------
__global__ void pin_zero_kernel(int n) {
    int i = blockIdx.x * blockDim.x + threadIdx.x;
    if (i < n) { g_sum[i] = 0.0f; g_sq[i] = 0.0f; }
}

__global__ void pin_reduce_scalar(const float* __restrict__ x,
                                  const int*   __restrict__ seqlen, int D) {
    const int b = blockIdx.y;
    const int s = seqlen[b];
    const int e = seqlen[b + 1];
    const int L = e - s;
    const int nb = gridDim.x;
    const int chunk = (L + nb - 1) / nb;
    long long r0 = (long long)s + (long long)blockIdx.x * chunk;
    long long r1 = (long long)s + (long long)min((long long)L,
                                                 (long long)(blockIdx.x + 1) * (long long)chunk);
    for (int d = threadIdx.x; d < D; d += blockDim.x) {
        float sum = 0.f, sq = 0.f;
        for (long long r = r0; r < r1; r++) {
            float v = x[r * D + d];
            sum += v; sq += v * v;
        }
        atomicAdd(&g_sum[b * D + d], sum);
        atomicAdd(&g_sq [b * D + d], sq);
    }
}

__global__ void pin_finalize_scalar(const int*   __restrict__ seqlen,
                                    const float* __restrict__ w,
                                    const float* __restrict__ bias,
                                    int B, int D) {
    int i = blockIdx.x * blockDim.x + threadIdx.x;
    if (i >= B * D) return;
    int b = i / D;
    int d = i - b * D;
    float denom = fmaxf((float)(seqlen[b + 1] - seqlen[b]), 1.0f);
    float mean  = g_sum[i] / denom;
    float var   = fmaxf(g_sq[i] / denom - mean * mean, 0.0f);
    float sc = rsqrtf(var + PIN_EPS) * w[d];
    g_scale[i] = sc;
    g_shift[i] = bias[d] - mean * sc;
}

__global__ void pin_norm_scalar(const float* __restrict__ x,
                                const int*   __restrict__ seqlen,
                                float*       __restrict__ out, int D) {
    const int b = blockIdx.y;
    const int s = seqlen[b];
    const int e = seqlen[b + 1];
    const int L = e - s;
    const int nb = gridDim.x;
    const int chunk = (L + nb - 1) / nb;
    long long r0 = (long long)s + (long long)blockIdx.x * chunk;
    long long r1 = (long long)s + (long long)min((long long)L,
                                                 (long long)(blockIdx.x + 1) * (long long)chunk);
    for (long long r = r0; r < r1; r++) {
        for (int d = threadIdx.x; d < D; d += blockDim.x) {
            float v = x[r * D + d];
            out[r * D + d] = fmaf(v, g_scale[b * D + d], g_shift[b * D + d]);
        }
    }
}

extern "C" void kernel_launch(void* const* d_in, const int* in_sizes, int n_in,
                              void* d_out, int out_size) {
    const float* x      = (const float*)d_in[0];
    const int*   seqlen = (const int*)  d_in[1];
    const float* weight = (const float*)d_in[2];
    const float* bias   = (const float*)d_in[3];
    float*       out    = (float*)d_out;

    const int D  = in_sizes[2];          // weight is [1, D]
    const int B  = in_sizes[1] - 1;      // seqlen is [B+1]
    const long long N = (D > 0) ? (long long)in_sizes[0] / D : 0;
    const int BD = B * D;

    const int D4 = D / 4;
    const bool vec_ok = (D > 0) && (D % 4 == 0) && (D4 >= 1) && (D4 <= 256) &&
                        (BD > 0) && (BD <= PIN_MAXBD);

    if (vec_ok) {
        // ---- reduce: one resident wave (R7 config) ----
        int dev = 0, sms = 0, per_sm = 0;
        cudaGetDevice(&dev);
        cudaDeviceGetAttribute(&sms, cudaDevAttrMultiProcessorCount, dev);
        cudaOccupancyMaxActiveBlocksPerMultiprocessor(&per_sm, pin_reduce_kernel,
                                                      256, 0);
        if (sms <= 0) sms = 148;
        if (per_sm <= 0) per_sm = 4;
        int rchunks = (sms * per_sm) / B;            // one wave total
        if (rchunks < 1) rchunks = 1;
        long long avg_rows = (N + B - 1) / B;
        if ((long long)rchunks > avg_rows && avg_rows > 0)
            rchunks = (int)avg_rows;
        while ((long long)rchunks * BD > PIN_PARTCAP && rchunks > 1)
            rchunks >>= 1;

        // ---- norm: R3 config (~4096 blocks) ----
        int nchunks = (4096 + B - 1) / B;
        if ((long long)nchunks > avg_rows && avg_rows > 0)
            nchunks = (int)avg_rows;
        if (nchunks < 1) nchunks = 1;

        dim3 rgrid(rchunks, B);
        dim3 ngrid(nchunks, B);

        pin_reduce_kernel<<<rgrid, 256>>>(x, seqlen, D4, BD);
        pin_norm_kernel<<<ngrid, 256>>>(x, seqlen, weight, bias, out,
                                        D4, BD, rchunks);
        return;
    }

    // ---- Fallback: scalar 4-kernel pipeline (any shape) ----
    {
        int threads = 256;
        int blocks = (BD + threads - 1) / threads;
        if (blocks < 1) blocks = 1;
        pin_zero_kernel<<<blocks, threads>>>(BD);
    }
    int Bx = (B > 0) ? B : 1;
    int ch = (4096 + Bx - 1) / Bx;
    long long avg_rows = (N + Bx - 1) / Bx;
    if ((long long)ch > avg_rows && avg_rows > 0) ch = (int)avg_rows;
    if (ch < 1) ch = 1;
    dim3 grid(ch, Bx);
    pin_reduce_scalar<<<grid, 256>>>(x, seqlen, D);
    {
        int threads = 256;
        int blocks = (BD + threads - 1) / threads;
        if (blocks < 1) blocks = 1;
        pin_finalize_scalar<<<blocks, threads>>>(seqlen, weight, bias, B, D);
    }
    pin_norm_scalar<<<grid, 256>>>(x, seqlen, out, D);
}

// round 15
// speedup vs baseline: 1.1142x; 1.0895x over previous
#include <cuda_runtime.h>
#include <cuda_bf16.h>

// PointInstanceNorm — R7 three-kernel structure (best: 250.4us) + PDL.
// x: [N,D] fp32; seqlen: [B+1] cumulative; weight/bias: [D].
// out[i,d] = (x[i,d]-mean[b,d]) * rsqrt(var[b,d]+eps) * w[d] + bias[d].
//
// R9-13 lesson (twice): fusing finalize into either streaming kernel costs
// 20-30us; the streaming bodies must stay untouched. This round keeps the
// R7 kernels byte-identical and hides the inter-kernel launch gaps with
// Programmatic Dependent Launch: finalize and norm are launched with
// programmatic stream serialization and call cudaGridDependencySynchronize()
// at their top, so their blocks are resident before the predecessor drains.

#define PIN_EPS 1e-5f
#define PIN_MAXBD   (1 << 20)
#define PIN_PARTCAP (1 << 22)

__device__ float g_psum [PIN_PARTCAP];
__device__ float g_psq  [PIN_PARTCAP];
__device__ float g_scale[PIN_MAXBD];
__device__ float g_shift[PIN_MAXBD];
// scalar-fallback scratch
__device__ float g_sum[PIN_MAXBD];
__device__ float g_sq [PIN_MAXBD];

// ---------------------------------------------------------------------------
// Pass 1: reduce — EXACT R7 form. grid=(chunks,B) one wave, block=256,
// 2-way unroll, per-(chunk,b) partials, no atomics.
// ---------------------------------------------------------------------------
__global__ void __launch_bounds__(256)
pin_reduce_kernel(const float* __restrict__ x,
                  const int*   __restrict__ seqlen,
                  int D4, int BD) {
    const int c  = blockIdx.x;
    const int b  = blockIdx.y;
    const long long s = seqlen[b];
    const long long e = seqlen[b + 1];
    const int L  = (int)(e - s);
    const int nb = gridDim.x;
    const int chunk = (L + nb - 1) / nb;
    const long long r0 = s + (long long)c * chunk;
    const long long r1 = s + (long long)min((long long)L,
                                            (long long)(c + 1) * (long long)chunk);
    const int lane = threadIdx.x % D4;
    const int grp  = threadIdx.x / D4;
    const int ngrp = blockDim.x / D4;
    const int D    = D4 * 4;

    float4 s0 = make_float4(0.f, 0.f, 0.f, 0.f), s1 = s0;
    float4 q0 = s0, q1 = s0;

    if (grp < ngrp) {
        const float4* __restrict__ x4 = (const float4*)x;
        const long long step = ngrp;
        long long r = r0 + grp;
        for (; r + step < r1; r += 2 * step) {
            float4 v0 = x4[(r       ) * D4 + lane];
            float4 v1 = x4[(r + step) * D4 + lane];
            s0.x += v0.x; s0.y += v0.y; s0.z += v0.z; s0.w += v0.w;
            q0.x += v0.x * v0.x; q0.y += v0.y * v0.y;
            q0.z += v0.z * v0.z; q0.w += v0.w * v0.w;
            s1.x += v1.x; s1.y += v1.y; s1.z += v1.z; s1.w += v1.w;
            q1.x += v1.x * v1.x; q1.y += v1.y * v1.y;
            q1.z += v1.z * v1.z; q1.w += v1.w * v1.w;
        }
        if (r < r1) {
            float4 v = x4[r * D4 + lane];
            s0.x += v.x; s0.y += v.y; s0.z += v.z; s0.w += v.w;
            q0.x += v.x * v.x; q0.y += v.y * v.y;
            q0.z += v.z * v.z; q0.w += v.w * v.w;
        }
    }
    s0.x += s1.x; s0.y += s1.y; s0.z += s1.z; s0.w += s1.w;
    q0.x += q1.x; q0.y += q1.y; q0.z += q1.z; q0.w += q1.w;

    __shared__ float4 sh_s[256];
    __shared__ float4 sh_q[256];
    sh_s[threadIdx.x] = s0;
    sh_q[threadIdx.x] = q0;
    __syncthreads();

    if (grp == 0) {
        for (int g = 1; g < ngrp; g++) {
            float4 a  = sh_s[g * D4 + lane];
            float4 cq = sh_q[g * D4 + lane];
            s0.x += a.x;  s0.y += a.y;  s0.z += a.z;  s0.w += a.w;
            q0.x += cq.x; q0.y += cq.y; q0.z += cq.z; q0.w += cq.w;
        }
        const long long o = (long long)c * BD + b * D + lane * 4;
        ((float4*)(g_psum + o))[0] = s0;
        ((float4*)(g_psq  + o))[0] = q0;
    }
}

// ---------------------------------------------------------------------------
// Finalize: sum partials over chunks -> scale/shift. PDL: waits on reduce.
// ---------------------------------------------------------------------------
__global__ void pin_finalize_kernel(const int*   __restrict__ seqlen,
                                    const float* __restrict__ w,
                                    const float* __restrict__ bias,
                                    int B, int D, int chunks) {
    int i = blockIdx.x * blockDim.x + threadIdx.x;
    int BD = B * D;

#if __CUDA_ARCH__ >= 900
    cudaGridDependencySynchronize();
#endif
    if (i >= BD) return;
    int b = i / D;
    int d = i - b * D;

    float sum = 0.f, sq = 0.f;
    for (int c = 0; c < chunks; c++) {
        long long o = (long long)c * BD + i;
        sum += g_psum[o];
        sq  += g_psq [o];
    }
    float denom = fmaxf((float)(seqlen[b + 1] - seqlen[b]), 1.0f);
    float mean  = sum / denom;
    float var   = fmaxf(sq / denom - mean * mean, 0.0f);
    float sc = rsqrtf(var + PIN_EPS) * w[d];
    g_scale[i] = sc;
    g_shift[i] = bias[d] - mean * sc;
}

// ---------------------------------------------------------------------------
// Pass 2: normalize — EXACT R3/R7 streaming form. PDL: waits on finalize
// after doing all dependency-free setup.
// ---------------------------------------------------------------------------
__global__ void __launch_bounds__(256)
pin_norm_kernel(const float* __restrict__ x,
                const int*   __restrict__ seqlen,
                float*       __restrict__ out,
                int D4) {
    const int b = blockIdx.y;
    const long long s = seqlen[b];
    const long long e = seqlen[b + 1];
    const int L  = (int)(e - s);
    const int nb = gridDim.x;
    const int chunk = (L + nb - 1) / nb;
    const long long r0 = s + (long long)blockIdx.x * chunk;
    const long long r1 = s + (long long)min((long long)L,
                                            (long long)(blockIdx.x + 1) * (long long)chunk);
    const int lane = threadIdx.x % D4;
    const int grp  = threadIdx.x / D4;
    const int ngrp = blockDim.x / D4;
    if (grp >= ngrp) return;

#if __CUDA_ARCH__ >= 900
    cudaGridDependencySynchronize();     // g_scale/g_shift now valid
#endif
    const float4 sc = ((const float4*)g_scale)[b * D4 + lane];
    const float4 sh = ((const float4*)g_shift)[b * D4 + lane];
    const float4* __restrict__ x4 = (const float4*)x;
    float4* __restrict__ o4 = (float4*)out;

    for (long long r = r0 + grp; r < r1; r += ngrp) {
        float4 v = x4[r * D4 + lane];
        float4 o;
        o.x = fmaf(v.x, sc.x, sh.x);
        o.y = fmaf(v.y, sc.y, sh.y);
        o.z = fmaf(v.z, sc.z, sh.z);
        o.w = fmaf(v.w, sc.w, sh.w);
        o4[r * D4 + lane] = o;
    }
}

// ---------------------------------------------------------------------------
// Scalar fallback (any shape).
// ---------------------------------------------------------------------------
__global__ void pin_zero_kernel(int n) {
    int i = blockIdx.x * blockDim.x + threadIdx.x;
    if (i < n) { g_sum[i] = 0.0f; g_sq[i] = 0.0f; }
}

__global__ void pin_reduce_scalar(const float* __restrict__ x,
                                  const int*   __restrict__ seqlen, int D) {
    const int b = blockIdx.y;
    const int s = seqlen[b];
    const int e = seqlen[b + 1];
    const int L = e - s;
    const int nb = gridDim.x;
    const int chunk = (L + nb - 1) / nb;
    long long r0 = (long long)s + (long long)blockIdx.x * chunk;
    long long r1 = (long long)s + (long long)min((long long)L,
                                                 (long long)(blockIdx.x + 1) * (long long)chunk);
    for (int d = threadIdx.x; d < D; d += blockDim.x) {
        float sum = 0.f, sq = 0.f;
        for (long long r = r0; r < r1; r++) {
            float v = x[r * D + d];
            sum += v; sq += v * v;
        }
        atomicAdd(&g_sum[b * D + d], sum);
        atomicAdd(&g_sq [b * D + d], sq);
    }
}

__global__ void pin_finalize_scalar(const int*   __restrict__ seqlen,
                                    const float* __restrict__ w,
                                    const float* __restrict__ bias,
                                    int B, int D) {
    int i = blockIdx.x * blockDim.x + threadIdx.x;
    if (i >= B * D) return;
    int b = i / D;
    int d = i - b * D;
    float denom = fmaxf((float)(seqlen[b + 1] - seqlen[b]), 1.0f);
    float mean  = g_sum[i] / denom;
    float var   = fmaxf(g_sq[i] / denom - mean * mean, 0.0f);
    float sc = rsqrtf(var + PIN_EPS) * w[d];
    g_scale[i] = sc;
    g_shift[i] = bias[d] - mean * sc;
}

__global__ void pin_norm_scalar(const float* __restrict__ x,
                                const int*   __restrict__ seqlen,
                                float*       __restrict__ out, int D) {
    const int b = blockIdx.y;
    const int s = seqlen[b];
    const int e = seqlen[b + 1];
    const int L = e - s;
    const int nb = gridDim.x;
    const int chunk = (L + nb - 1) / nb;
    long long r0 = (long long)s + (long long)blockIdx.x * chunk;
    long long r1 = (long long)s + (long long)min((long long)L,
                                                 (long long)(blockIdx.x + 1) * (long long)chunk);
    for (long long r = r0; r < r1; r++) {
        for (int d = threadIdx.x; d < D; d += blockDim.x) {
            float v = x[r * D + d];
            out[r * D + d] = fmaf(v, g_scale[b * D + d], g_shift[b * D + d]);
        }
    }
}

// Launch helper: kernel with programmatic stream serialization (PDL).
template <typename... Args>
static void launch_pdl(void (*kern)(Args...), dim3 grid, dim3 block,
                       Args... args) {
    cudaLaunchConfig_t cfg = {};
    cfg.gridDim = grid;
    cfg.blockDim = block;
    cfg.dynamicSmemBytes = 0;
    cfg.stream = 0;
    cudaLaunchAttribute attr[1];
    attr[0].id = cudaLaunchAttributeProgrammaticStreamSerialization;
    attr[0].val.programmaticStreamSerializationAllowed = 1;
    cfg.attrs = attr;
    cfg.numAttrs = 1;
    cudaError_t err = cudaLaunchKernelEx(&cfg, kern, args...);
    if (err != cudaSuccess) {
        // Fallback: plain serial launch (same semantics, no overlap)
        cudaGetLastError();
        void* params[] = { (void*)&args... };
        cudaLaunchKernel((const void*)kern, grid, block, params, 0, 0);
    }
}

extern "C" void kernel_launch(void* const* d_in, const int* in_sizes, int n_in,
                              void* d_out, int out_size) {
    const float* x      = (const float*)d_in[0];
    const int*   seqlen = (const int*)  d_in[1];
    const float* weight = (const float*)d_in[2];
    const float* bias   = (const float*)d_in[3];
    float*       out    = (float*)d_out;

    const int D  = in_sizes[2];          // weight is [1, D]
    const int B  = in_sizes[1] - 1;      // seqlen is [B+1]
    const long long N = (D > 0) ? (long long)in_sizes[0] / D : 0;
    const int BD = B * D;

    const int D4 = D / 4;
    const bool vec_ok = (D > 0) && (D % 4 == 0) && (D4 >= 1) && (D4 <= 256) &&
                        (BD > 0) && (BD <= PIN_MAXBD);

    if (vec_ok) {
        // ---- reduce: one resident wave (R7 config) ----
        int dev = 0, sms = 0, per_sm = 0;
        cudaGetDevice(&dev);
        cudaDeviceGetAttribute(&sms, cudaDevAttrMultiProcessorCount, dev);
        cudaOccupancyMaxActiveBlocksPerMultiprocessor(&per_sm, pin_reduce_kernel,
                                                      256, 0);
        if (sms <= 0) sms = 148;
        if (per_sm <= 0) per_sm = 4;
        int rchunks = (sms * per_sm) / B;            // one wave total
        if (rchunks < 1) rchunks = 1;
        long long avg_rows = (N + B - 1) / B;
        if ((long long)rchunks > avg_rows && avg_rows > 0)
            rchunks = (int)avg_rows;
        while ((long long)rchunks * BD > PIN_PARTCAP && rchunks > 1)
            rchunks >>= 1;

        // ---- norm: R3 config (~4096 blocks) ----
        int nchunks = (4096 + B - 1) / B;
        if ((long long)nchunks > avg_rows && avg_rows > 0)
            nchunks = (int)avg_rows;
        if (nchunks < 1) nchunks = 1;

        dim3 rgrid(rchunks, B);
        dim3 ngrid(nchunks, B);

        pin_reduce_kernel<<<rgrid, 256>>>(x, seqlen, D4, BD);

        {
            int threads = 256;
            int blocks = (BD + threads - 1) / threads;
            launch_pdl(pin_finalize_kernel, dim3(blocks), dim3(threads),
                       seqlen, weight, bias, B, D, rchunks);
        }
        launch_pdl(pin_norm_kernel, ngrid, dim3(256),
                   x, seqlen, out, D4);
        return;
    }

    // ---- Fallback: scalar 4-kernel pipeline (any shape) ----
    {
        int threads = 256;
        int blocks = (BD + threads - 1) / threads;
        if (blocks < 1) blocks = 1;
        pin_zero_kernel<<<blocks, threads>>>(BD);
    }
    int Bx = (B > 0) ? B : 1;
    int ch = (4096 + Bx - 1) / Bx;
    long long avg_rows = (N + Bx - 1) / Bx;
    if ((long long)ch > avg_rows && avg_rows > 0) ch = (int)avg_rows;
    if (ch < 1) ch = 1;
    dim3 grid(ch, Bx);
    pin_reduce_scalar<<<grid, 256>>>(x, seqlen, D);
    {
        int threads = 256;
        int blocks = (BD + threads - 1) / threads;
        if (blocks < 1) blocks = 1;
        pin_finalize_scalar<<<blocks, threads>>>(seqlen, weight, bias, B, D);
    }
    pin_norm_scalar<<<grid, 256>>>(x, seqlen, out, D);
}